// round 12
// baseline (speedup 1.0000x reference)
#include <cuda_runtime.h>

#define B 8
#define S 64
#define V 50257
#define P 200
#define NCHUNK 5
#define THREADS 256
#define MWORDS 320            // max chunk span ~10056 floats -> 315 words, padded
#define INV_T  (1.0f/0.6f)
#define PEN    1.2f
#define INV_PEN (1.0f/1.2f)
#define BSTRIDE  ((size_t)S * V)

__device__ float g_pl[S * NCHUNK * B];   // partial sums (penalty included)

// Aligned vector range for (s, chunk c): v = a + 4g is 16B-aligned for every
// batch row (since (b*S+s)*V ≡ s mod 4 and BSTRIDE % 4 == 0).
__device__ __forceinline__ void chunk_range(int s, int c, int& a, int& G, int& v0, int& v1) {
    a = (4 - (s & 3)) & 3;
    G = (V - a) >> 2;
    const int g0 = (int)(((long long)c * G) / NCHUNK);
    const int g1 = (int)(((long long)(c + 1) * G) / NCHUNK);
    v0 = a + 4 * g0;
    v1 = a + 4 * g1;
}

__device__ __forceinline__ void build_mask(unsigned* smask, int* sprev,
                                           const int* __restrict__ prev,
                                           int s, int v0, int v1) {
    for (int i = threadIdx.x; i < MWORDS; i += THREADS) smask[i] = 0u;
    __syncthreads();
    for (int t = threadIdx.x; t < P; t += THREADS) {
        const int tok = prev[s * P + t];
        sprev[t] = tok;
        if (tok >= v0 && tok < v1) {
            const int r = tok - v0;
            atomicOr(&smask[r >> 5], 1u << (r & 31));
        }
    }
}

// all_neg over all 8 batch rows at position v (rare path; ~0.4% of elements).
__device__ __forceinline__ float penal_fac(const float* __restrict__ logits,
                                           int s, int v) {
    bool allneg = true;
#pragma unroll
    for (int b = 0; b < B; b++)
        allneg = allneg && (logits[((size_t)b * S + s) * V + v] < 0.0f);
    return (allneg ? PEN : INV_PEN) * INV_T;
}

// -------- k_exp: exp(penalized/T) -> out (unnormalized, L2-resident) + sums.
__global__ __launch_bounds__(THREADS, 5) void k_exp(const float* __restrict__ logits,
                                                    const int* __restrict__ prev,
                                                    float* __restrict__ out) {
    const int c = blockIdx.x % NCHUNK;
    const int t = blockIdx.x / NCHUNK;
    const int b0 = (t & 1) * 4;
    const int s = t >> 1;
    int a, G, v0, v1;
    chunk_range(s, c, a, G, v0, v1);

    __shared__ unsigned smask[MWORDS];
    __shared__ int sprev[P];
    build_mask(smask, sprev, prev, s, v0, v1);
    __syncthreads();

    const float* base[4];
    float* obase[4];
#pragma unroll
    for (int i = 0; i < 4; i++) {
        base[i] = logits + ((size_t)(b0 + i) * S + s) * V;
        obase[i] = out + ((size_t)(b0 + i) * S + s) * V;
    }

    float sum[4] = {0.0f, 0.0f, 0.0f, 0.0f};
    for (int v = v0 + 4 * (int)threadIdx.x; v < v1; v += 4 * THREADS) {
        const int r = v - v0;
        const unsigned bits4 = (smask[r >> 5] >> (r & 31)) & 0xFu;
        float4 x[4];
#pragma unroll
        for (int i = 0; i < 4; i++) x[i] = __ldcs((const float4*)(base[i] + v));
        float fac0 = INV_T, fac1 = INV_T, fac2 = INV_T, fac3 = INV_T;
        if (bits4 != 0u) {                              // rare (~0.4% of groups)
            if (bits4 & 1u) fac0 = penal_fac(logits, s, v + 0);
            if (bits4 & 2u) fac1 = penal_fac(logits, s, v + 1);
            if (bits4 & 4u) fac2 = penal_fac(logits, s, v + 2);
            if (bits4 & 8u) fac3 = penal_fac(logits, s, v + 3);
        }
#pragma unroll
        for (int i = 0; i < 4; i++) {
            float4 e;
            e.x = __expf(x[i].x * fac0);
            e.y = __expf(x[i].y * fac1);
            e.z = __expf(x[i].z * fac2);
            e.w = __expf(x[i].w * fac3);
            sum[i] += e.x + e.y + e.z + e.w;
            *(float4*)(obase[i] + v) = e;               // default: stay dirty in L2
        }
    }

    if (c == 0) {                         // unaligned head/tail scalars (<=6)
        const int tail0 = a + 4 * G;
        const int cnt = a + (V - tail0);
        if ((int)threadIdx.x < cnt) {
            const int v = ((int)threadIdx.x < a) ? (int)threadIdx.x
                                                 : tail0 + ((int)threadIdx.x - a);
            bool hit = false;
            for (int p = 0; p < P; p++) hit |= (sprev[p] == v);
            const float fac = hit ? penal_fac(logits, s, v) : INV_T;
#pragma unroll
            for (int i = 0; i < 4; i++) {
                const float e = __expf(base[i][v] * fac);
                sum[i] += e;
                obase[i][v] = e;
            }
        }
    }

#pragma unroll
    for (int i = 0; i < 4; i++) {
#pragma unroll
        for (int off = 16; off; off >>= 1)
            sum[i] += __shfl_xor_sync(0xffffffffu, sum[i], off);
    }
    __shared__ float ssum[THREADS / 32][4];
    const int warp = threadIdx.x >> 5;
    if ((threadIdx.x & 31) == 0) {
#pragma unroll
        for (int i = 0; i < 4; i++) ssum[warp][i] = sum[i];
    }
    __syncthreads();
    if (threadIdx.x < 4) {
        const int i = threadIdx.x;
        float L = 0.0f;
#pragma unroll
        for (int w = 0; w < THREADS / 32; w++) L += ssum[w][i];
        g_pl[(s * NCHUNK + c) * B + b0 + i] = L;
    }
}

// -------- k_scale: in-place normalize. No exp, no mask; reads hit dirty L2.
__global__ __launch_bounds__(THREADS, 5) void k_scale(float* __restrict__ out) {
    const int c = blockIdx.x % NCHUNK;
    const int t = blockIdx.x / NCHUNK;
    const int b0 = (t & 1) * 4;
    const int s = t >> 1;
    int a, G, v0, v1;
    chunk_range(s, c, a, G, v0, v1);

    __shared__ float sR[4];
    if (threadIdx.x < 4) {
        const int b = b0 + (int)threadIdx.x;
        float L = 0.0f;
#pragma unroll
        for (int cc = 0; cc < NCHUNK; cc++) L += g_pl[(s * NCHUNK + cc) * B + b];
        sR[threadIdx.x] = 1.0f / L;
    }
    __syncthreads();
    float R[4];
#pragma unroll
    for (int i = 0; i < 4; i++) R[i] = sR[i];

    float* obase[4];
#pragma unroll
    for (int i = 0; i < 4; i++) obase[i] = out + ((size_t)(b0 + i) * S + s) * V;

    for (int v = v0 + 4 * (int)threadIdx.x; v < v1; v += 4 * THREADS) {
#pragma unroll
        for (int i = 0; i < 4; i++) {
            float4 o = *(const float4*)(obase[i] + v);   // dirty-L2 hit
            o.x *= R[i]; o.y *= R[i]; o.z *= R[i]; o.w *= R[i];
            __stcs((float4*)(obase[i] + v), o);          // final data: stream out
        }
    }

    if (c == 0) {
        const int tail0 = a + 4 * G;
        const int cnt = a + (V - tail0);
        if ((int)threadIdx.x < cnt) {
            const int v = ((int)threadIdx.x < a) ? (int)threadIdx.x
                                                 : tail0 + ((int)threadIdx.x - a);
#pragma unroll
            for (int i = 0; i < 4; i++) obase[i][v] *= R[i];
        }
    }
}

extern "C" void kernel_launch(void* const* d_in, const int* in_sizes, int n_in,
                              void* d_out, int out_size) {
    const float* logits = (const float*)d_in[0];
    const int* prev = (const int*)d_in[1];
    float* out = (float*)d_out;
    (void)in_sizes; (void)n_in; (void)out_size;

    k_exp<<<S * 2 * NCHUNK, THREADS>>>(logits, prev, out);
    k_scale<<<S * 2 * NCHUNK, THREADS>>>(out);
}

// round 13
// speedup vs baseline: 1.0624x; 1.0624x over previous
#include <cuda_runtime.h>

#define B 8
#define S 64
#define V 50257
#define P 200
#define NCHUNK 3
#define GRID (S * 2 * NCHUNK)    // 384 CTAs, single resident wave at occ>=3/SM
#define THREADS 256
#define MWORDS 528               // max chunk span ~16760 floats -> 524 words
#define INV_T  (1.0f/0.6f)
#define PEN    1.2f
#define INV_PEN (1.0f/1.2f)
#define BSTRIDE  ((size_t)S * V)

__device__ float g_pl[S * NCHUNK * B];     // phase-1 partial sums
__device__ unsigned g_arrive;              // monotonic barrier ticket (never reset)

// Aligned vector range for (s, chunk c): v = a + 4g is 16B-aligned for every
// batch row (since (b*S+s)*V ≡ s mod 4 and BSTRIDE % 4 == 0).
__device__ __forceinline__ void chunk_range(int s, int c, int& a, int& G, int& v0, int& v1) {
    a = (4 - (s & 3)) & 3;
    G = (V - a) >> 2;
    const int g0 = (int)(((long long)c * G) / NCHUNK);
    const int g1 = (int)(((long long)(c + 1) * G) / NCHUNK);
    v0 = a + 4 * g0;
    v1 = a + 4 * g1;
}

// all_neg over all 8 batch rows at position v (rare path; ~0.4% of elements).
__device__ __forceinline__ float penal_fac(const float* __restrict__ logits,
                                           int s, int v) {
    bool allneg = true;
#pragma unroll
    for (int b = 0; b < B; b++)
        allneg = allneg && (logits[((size_t)b * S + s) * V + v] < 0.0f);
    return (allneg ? PEN : INV_PEN) * INV_T;
}

__global__ __launch_bounds__(THREADS, 3) void k_fused(const float* __restrict__ logits,
                                                      const int* __restrict__ prev,
                                                      float* __restrict__ out) {
    const int c = blockIdx.x % NCHUNK;
    const int t = blockIdx.x / NCHUNK;
    const int b0 = (t & 1) * 4;
    const int s = t >> 1;
    int a, G, v0, v1;
    chunk_range(s, c, a, G, v0, v1);

    __shared__ unsigned smask[MWORDS];
    __shared__ int sprev[P];
    __shared__ float ssum[THREADS / 32][4];
    __shared__ float sR[4];

    // ---- mask build (survives into phase 2) ----
    for (int i = threadIdx.x; i < MWORDS; i += THREADS) smask[i] = 0u;
    __syncthreads();
    for (int p = threadIdx.x; p < P; p += THREADS) {
        const int tok = prev[s * P + p];
        sprev[p] = tok;
        if (tok >= v0 && tok < v1) {
            const int r = tok - v0;
            atomicOr(&smask[r >> 5], 1u << (r & 31));
        }
    }
    __syncthreads();

    const float* base[4];
    float* obase[4];
#pragma unroll
    for (int i = 0; i < 4; i++) {
        base[i] = logits + ((size_t)(b0 + i) * S + s) * V;
        obase[i] = out + ((size_t)(b0 + i) * S + s) * V;
    }

    // ================= phase 1: sums (default-cached reads fill L2) =========
    float sum[4] = {0.0f, 0.0f, 0.0f, 0.0f};
    for (int v = v0 + 4 * (int)threadIdx.x; v < v1; v += 4 * THREADS) {
        const int r = v - v0;
        const unsigned bits4 = (smask[r >> 5] >> (r & 31)) & 0xFu;
        float4 x[4];
#pragma unroll
        for (int i = 0; i < 4; i++) x[i] = *(const float4*)(base[i] + v);
        float fac0 = INV_T, fac1 = INV_T, fac2 = INV_T, fac3 = INV_T;
        if (bits4 != 0u) {
            if (bits4 & 1u) fac0 = penal_fac(logits, s, v + 0);
            if (bits4 & 2u) fac1 = penal_fac(logits, s, v + 1);
            if (bits4 & 4u) fac2 = penal_fac(logits, s, v + 2);
            if (bits4 & 8u) fac3 = penal_fac(logits, s, v + 3);
        }
#pragma unroll
        for (int i = 0; i < 4; i++)
            sum[i] += __expf(x[i].x * fac0) + __expf(x[i].y * fac1)
                    + __expf(x[i].z * fac2) + __expf(x[i].w * fac3);
    }
    if (c == 0) {                          // unaligned head/tail scalars (<=6)
        const int tail0 = a + 4 * G;
        const int cnt = a + (V - tail0);
        if ((int)threadIdx.x < cnt) {
            const int v = ((int)threadIdx.x < a) ? (int)threadIdx.x
                                                 : tail0 + ((int)threadIdx.x - a);
            bool hit = false;
            for (int p = 0; p < P; p++) hit |= (sprev[p] == v);
            const float fac = hit ? penal_fac(logits, s, v) : INV_T;
#pragma unroll
            for (int i = 0; i < 4; i++) sum[i] += __expf(base[i][v] * fac);
        }
    }

#pragma unroll
    for (int i = 0; i < 4; i++) {
#pragma unroll
        for (int off = 16; off; off >>= 1)
            sum[i] += __shfl_xor_sync(0xffffffffu, sum[i], off);
    }
    const int warp = threadIdx.x >> 5;
    if ((threadIdx.x & 31) == 0) {
#pragma unroll
        for (int i = 0; i < 4; i++) ssum[warp][i] = sum[i];
    }
    __syncthreads();
    if (threadIdx.x < 4) {
        const int i = threadIdx.x;
        float L = 0.0f;
#pragma unroll
        for (int w = 0; w < THREADS / 32; w++) L += ssum[w][i];
        g_pl[(s * NCHUNK + c) * B + b0 + i] = L;
    }

    // ================= grid barrier (single resident wave) ==================
    __threadfence();
    __syncthreads();
    if (threadIdx.x == 0) {
        const unsigned ticket = atomicAdd(&g_arrive, 1u);
        const unsigned target = (ticket / GRID + 1u) * GRID;
        while (*(volatile unsigned*)&g_arrive < target) { __nanosleep(64); }
    }
    __syncthreads();

    // ================= phase 2: normalize + write (reads hit L2) ============
    if (threadIdx.x < 4) {
        const int b = b0 + (int)threadIdx.x;
        float L = 0.0f;
#pragma unroll
        for (int cc = 0; cc < NCHUNK; cc++)
            L += __ldcg(&g_pl[(s * NCHUNK + cc) * B + b]);
        sR[threadIdx.x] = 1.0f / L;
    }
    __syncthreads();
    float R[4];
#pragma unroll
    for (int i = 0; i < 4; i++) R[i] = sR[i];

    for (int v = v0 + 4 * (int)threadIdx.x; v < v1; v += 4 * THREADS) {
        const int r = v - v0;
        const unsigned bits4 = (smask[r >> 5] >> (r & 31)) & 0xFu;
        float4 x[4];
#pragma unroll
        for (int i = 0; i < 4; i++) x[i] = *(const float4*)(base[i] + v);   // L2 hit
        float fac0 = INV_T, fac1 = INV_T, fac2 = INV_T, fac3 = INV_T;
        if (bits4 != 0u) {
            if (bits4 & 1u) fac0 = penal_fac(logits, s, v + 0);
            if (bits4 & 2u) fac1 = penal_fac(logits, s, v + 1);
            if (bits4 & 4u) fac2 = penal_fac(logits, s, v + 2);
            if (bits4 & 8u) fac3 = penal_fac(logits, s, v + 3);
        }
#pragma unroll
        for (int i = 0; i < 4; i++) {
            float4 o;
            o.x = __expf(x[i].x * fac0) * R[i];
            o.y = __expf(x[i].y * fac1) * R[i];
            o.z = __expf(x[i].z * fac2) * R[i];
            o.w = __expf(x[i].w * fac3) * R[i];
            __stcs((float4*)(obase[i] + v), o);         // stream out, spare L2
        }
    }
    if (c == 0) {
        const int tail0 = a + 4 * G;
        const int cnt = a + (V - tail0);
        if ((int)threadIdx.x < cnt) {
            const int v = ((int)threadIdx.x < a) ? (int)threadIdx.x
                                                 : tail0 + ((int)threadIdx.x - a);
            bool hit = false;
            for (int p = 0; p < P; p++) hit |= (sprev[p] == v);
            const float fac = hit ? penal_fac(logits, s, v) : INV_T;
#pragma unroll
            for (int i = 0; i < 4; i++)
                obase[i][v] = __expf(base[i][v] * fac) * R[i];
        }
    }
}

extern "C" void kernel_launch(void* const* d_in, const int* in_sizes, int n_in,
                              void* d_out, int out_size) {
    const float* logits = (const float*)d_in[0];
    const int* prev = (const int*)d_in[1];
    float* out = (float*)d_out;
    (void)in_sizes; (void)n_in; (void)out_size;

    k_fused<<<GRID, THREADS>>>(logits, prev, out);
}